// round 7
// baseline (speedup 1.0000x reference)
#include <cuda_runtime.h>
#include <math.h>

#define NN 100000
#define DD 128
#define HH 16
#define EE 1600000
#define BB 16384
#define FULL 0xffffffffu

#define DEG_BLOCKS   ((EE / 4 + 255) / 256)   // 1563
#define FILL_BLOCKS  ((EE / 4 + 255) / 256)   // 1563
#define PROJ_TOTAL   ((NN + 127) / 128)       // 782
#define PROJ_A       391
#define PROJ_B       (PROJ_TOTAL - PROJ_A)    // 391
#define SCAN_BLOCKS  98

typedef unsigned long long u64;

// ---------------- scratch (device globals) ---------------------------------
__device__ int    g_degi[NN];
__device__ int    g_row [NN + 1];   // exclusive offsets; post-fill: row[n] = end(n)
__device__ float  g_inv [NN];
__device__ int    g_csr [EE];
__device__ float  g_y1  [NN * HH];
__device__ float  g_z1  [NN * HH];
__device__ float2 g_p   [NN];
__device__ float2 g_q   [NN];
__device__ float  g_s1  [NN];
__device__ float  g_s2  [NN];
__device__ float  g_u   [66];
__device__ float  g_partial[64];
__device__ int    g_flag[SCAN_BLOCKS + 1];   // chained-scan lookback flags
__device__ int    g_done;                    // loss last-block counter

// f32x2 packed math (sm_100+)
#define PK(d, lo, hi)  asm("mov.b64 %0, {%1,%2};" : "=l"(d) : "f"(lo), "f"(hi))
#define UPK(lo, hi, s) asm("mov.b64 {%0,%1}, %2;" : "=f"(lo), "=f"(hi) : "l"(s))
#define FMA2(d, a, b)  asm("fma.rn.f32x2 %0, %1, %2, %0;" : "+l"(d) : "l"(a), "l"(b))

// ---------------- proj tile: y1 = x@w1_l, z1 = x@w1_r for 128 rows ----------
__device__ __forceinline__ void proj_tile(const float* __restrict__ x,
                                          const float* __restrict__ w1l,
                                          const float* __restrict__ w1r,
                                          int row0, float* sw, float* sxT) {
    const int tid = threadIdx.x;
    for (int i = tid; i < DD * 32; i += 256) {
        int k = i >> 5, j = i & 31;
        sw[i] = (j < 16) ? w1l[k * HH + j] : w1r[k * HH + (j - 16)];
    }

    const int rq = tid >> 3;
    const int g  = tid & 7;

    u64 accp[2][4];
#pragma unroll
    for (int i = 0; i < 2; i++)
#pragma unroll
        for (int j = 0; j < 4; j++) accp[i][j] = 0ull;

    const int rs = tid >> 3;
    const int q  = tid & 7;

    for (int kc = 0; kc < 4; kc++) {
        __syncthreads();
#pragma unroll
        for (int rr = rs; rr < 128; rr += 32) {
            int row = row0 + rr;
            float4 v = make_float4(0.f, 0.f, 0.f, 0.f);
            if (row < NN)
                v = reinterpret_cast<const float4*>(x + row * DD + kc * 32)[q];
            sxT[(q * 4 + 0) * 132 + rr] = v.x;
            sxT[(q * 4 + 1) * 132 + rr] = v.y;
            sxT[(q * 4 + 2) * 132 + rr] = v.z;
            sxT[(q * 4 + 3) * 132 + rr] = v.w;
        }
        __syncthreads();
#pragma unroll
        for (int kk = 0; kk < 32; kk++) {
            float4 xv = *reinterpret_cast<const float4*>(&sxT[kk * 132 + rq * 4]);
            float4 wv = *reinterpret_cast<const float4*>(&sw[(kc * 32 + kk) * 32 + g * 4]);
            u64 x01, x23, w0, w1, w2, w3;
            PK(x01, xv.x, xv.y);
            PK(x23, xv.z, xv.w);
            PK(w0, wv.x, wv.x);
            PK(w1, wv.y, wv.y);
            PK(w2, wv.z, wv.z);
            PK(w3, wv.w, wv.w);
            FMA2(accp[0][0], x01, w0); FMA2(accp[1][0], x23, w0);
            FMA2(accp[0][1], x01, w1); FMA2(accp[1][1], x23, w1);
            FMA2(accp[0][2], x01, w2); FMA2(accp[1][2], x23, w2);
            FMA2(accp[0][3], x01, w3); FMA2(accp[1][3], x23, w3);
        }
    }

    float acc[4][4];
#pragma unroll
    for (int j = 0; j < 4; j++) {
        UPK(acc[0][j], acc[1][j], accp[0][j]);
        UPK(acc[2][j], acc[3][j], accp[1][j]);
    }

#pragma unroll
    for (int i = 0; i < 4; i++) {
        int row = row0 + rq * 4 + i;
        if (row < NN) {
            float4 v = make_float4(acc[i][0], acc[i][1], acc[i][2], acc[i][3]);
            if (g < 4) reinterpret_cast<float4*>(g_y1 + row * HH)[g]     = v;
            else       reinterpret_cast<float4*>(g_z1 + row * HH)[g - 4] = v;
        }
    }
}

// ---------------- K_init: zero counters/flags + prep collapsed weights -----
__global__ void k_init(const float* __restrict__ w2l, const float* __restrict__ w2r,
                       const float* __restrict__ b2,  const float* __restrict__ wc) {
    if (blockIdx.x < 98) {
        int n = blockIdx.x * 1024 + threadIdx.x;
        if (n < NN) g_degi[n] = 0;
    } else {
        int t = threadIdx.x;
        if (t < 64) {
            int which = t >> 4, j = t & 15;
            const float* w = (which == 0 || which == 2) ? w2l : w2r;
            const float* c = (which < 2) ? wc : (wc + DD);
            float s = 0.f;
            for (int d = 0; d < DD; d++) s += w[j * DD + d] * c[d];
            g_u[which * 16 + j] = s;
        }
        if (t == 64) { float s = 0.f; for (int d = 0; d < DD; d++) s += b2[d] * wc[d];      g_u[64] = s; }
        if (t == 65) { float s = 0.f; for (int d = 0; d < DD; d++) s += b2[d] * wc[DD + d]; g_u[65] = s; }
        if (t >= 128 && t < 128 + SCAN_BLOCKS + 1) g_flag[t - 128] = 0;
        if (t == 256) g_done = 0;
    }
}

// ---------------- K_p1: proj part A + degree histogram ---------------------
__global__ void k_p1(const float* __restrict__ x,
                     const float* __restrict__ w1l,
                     const float* __restrict__ w1r,
                     const int*   __restrict__ dst) {
    __shared__ float sw[DD * 32];
    __shared__ float sxT[32 * 132];
    int b = blockIdx.x;
    if (b < PROJ_A) {
        proj_tile(x, w1l, w1r, b * 128, sw, sxT);
        return;
    }
    int idx = (b - PROJ_A) * 256 + threadIdx.x;
    if (idx < EE / 4) {
        int4 d = reinterpret_cast<const int4*>(dst)[idx];
        atomicAdd(&g_degi[d.x], 1);
        atomicAdd(&g_degi[d.y], 1);
        atomicAdd(&g_degi[d.z], 1);
        atomicAdd(&g_degi[d.w], 1);
    }
}

// ---------------- K_scan: single-pass chained scan + finalize ---------------
__global__ void k_scan() {
    __shared__ int ws[32];
    __shared__ int s_prefix;
    int tid = threadIdx.x, lane = tid & 31, w = tid >> 5;
    int n = blockIdx.x * 1024 + tid;
    int d = (n < NN) ? g_degi[n] : 0;
    int x = d;
#pragma unroll
    for (int o = 1; o < 32; o <<= 1) {
        int t = __shfl_up_sync(FULL, x, o);
        if (lane >= o) x += t;
    }
    if (lane == 31) ws[w] = x;
    __syncthreads();
    if (w == 0) {
        int b = ws[lane];
#pragma unroll
        for (int o = 1; o < 32; o <<= 1) {
            int t = __shfl_up_sync(FULL, b, o);
            if (lane >= o) b += t;
        }
        ws[lane] = b;
    }
    __syncthreads();
    int incl = x + (w > 0 ? ws[w - 1] : 0);

    // decoupled chained lookback: block b waits for prefix from block b-1
    if (tid == 0) {
        int prefix = 0;
        if (blockIdx.x > 0) {
            volatile int* f = &g_flag[blockIdx.x];
            int v;
            while ((v = *f) == 0) {}
            prefix = v - 1;
        }
        s_prefix = prefix;
        __threadfence();
        g_flag[blockIdx.x + 1] = prefix + ws[31] + 1;
    }
    __syncthreads();

    if (n < NN) {
        g_row[n] = s_prefix + incl - d;   // exclusive offset
        g_inv[n] = 1.f / (float)max(d, 1);
    }
}

// ---------------- K_p2: CSR fill + proj part B ------------------------------
// fill bumps g_row[d] directly; after completion g_row[n] == end(n).
__global__ void k_p2(const float* __restrict__ x,
                     const float* __restrict__ w1l,
                     const float* __restrict__ w1r,
                     const int*   __restrict__ src,
                     const int*   __restrict__ dst) {
    __shared__ float sw[DD * 32];
    __shared__ float sxT[32 * 132];
    int b = blockIdx.x;
    if (b >= FILL_BLOCKS) {
        proj_tile(x, w1l, w1r, (PROJ_A + (b - FILL_BLOCKS)) * 128, sw, sxT);
        return;
    }
    int idx = b * 256 + threadIdx.x;
    if (idx < EE / 4) {
        int4 s = reinterpret_cast<const int4*>(src)[idx];
        int4 d = reinterpret_cast<const int4*>(dst)[idx];
        int p0 = atomicAdd(&g_row[d.x], 1); g_csr[p0] = s.x;
        int p1 = atomicAdd(&g_row[d.y], 1); g_csr[p1] = s.y;
        int p2 = atomicAdd(&g_row[d.z], 1); g_csr[p2] = s.z;
        int p3 = atomicAdd(&g_row[d.w], 1); g_csr[p3] = s.w;
    }
}

// ---------------- K_gagg1: quad-gather y1 + fused h + contraction ----------
// 4 threads per node; lane c handles components c*4..c*4+3.
// CSR indices loaded once per quad (lane c loads j+c), broadcast with the
// QUAD-LOCAL mask: loop trip counts differ per quad within a warp, so the
// full-warp mask is illegal inside the loop.
__global__ void k_gagg1(const float* __restrict__ b1) {
    __shared__ float su[64];
    __shared__ float sb[16];
    int tid = threadIdx.x;
    if (tid < 64) su[tid] = g_u[tid];
    if (tid < 16) sb[tid] = b1[tid];
    __syncthreads();

    int t = blockIdx.x * 256 + tid;
    int n = t >> 2, c = t & 3;
    bool valid = (n < NN);
    int ncl = valid ? n : (NN - 1);        // clamp so all lanes stay active

    const unsigned qmask = 0xFu << (threadIdx.x & 28);  // this quad's 4 lanes

    int deg = g_degi[ncl];
    int end = g_row[ncl];                  // post-fill: end offset
    int beg = end - deg;
    float4 acc = make_float4(0.f, 0.f, 0.f, 0.f);
    int last = end - 1;
    for (int j = beg; j < end; j += 4) {
        int jj = min(j + c, last);
        int idx = g_csr[jj];
        int s0 = __shfl_sync(qmask, idx, 0, 4);
        int s1 = __shfl_sync(qmask, idx, 1, 4);
        int s2 = __shfl_sync(qmask, idx, 2, 4);
        int s3 = __shfl_sync(qmask, idx, 3, 4);
        float w1 = (j + 1 < end) ? 1.f : 0.f;
        float w2 = (j + 2 < end) ? 1.f : 0.f;
        float w3 = (j + 3 < end) ? 1.f : 0.f;
        float4 v0 = reinterpret_cast<const float4*>(g_y1 + (size_t)s0 * HH)[c];
        float4 v1 = reinterpret_cast<const float4*>(g_y1 + (size_t)s1 * HH)[c];
        float4 v2 = reinterpret_cast<const float4*>(g_y1 + (size_t)s2 * HH)[c];
        float4 v3 = reinterpret_cast<const float4*>(g_y1 + (size_t)s3 * HH)[c];
        acc.x += v0.x + fmaf(w1, v1.x, fmaf(w2, v2.x, w3 * v3.x));
        acc.y += v0.y + fmaf(w1, v1.y, fmaf(w2, v2.y, w3 * v3.y));
        acc.z += v0.z + fmaf(w1, v1.z, fmaf(w2, v2.z, w3 * v3.z));
        acc.w += v0.w + fmaf(w1, v1.w, fmaf(w2, v2.w, w3 * v3.w));
    }

    float inv = g_inv[ncl];
    float4 z = reinterpret_cast<const float4*>(g_z1 + (size_t)ncl * HH)[c];
    int j0 = c * 4;
    float h0 = fmaxf(acc.x * inv + sb[j0 + 0] + z.x, 0.f);
    float h1 = fmaxf(acc.y * inv + sb[j0 + 1] + z.y, 0.f);
    float h2 = fmaxf(acc.z * inv + sb[j0 + 2] + z.z, 0.f);
    float h3 = fmaxf(acc.w * inv + sb[j0 + 3] + z.w, 0.f);

    float p1 = h0 * su[j0]      + h1 * su[j0 + 1]  + h2 * su[j0 + 2]  + h3 * su[j0 + 3];
    float q1 = h0 * su[16 + j0] + h1 * su[17 + j0] + h2 * su[18 + j0] + h3 * su[19 + j0];
    float p2 = h0 * su[32 + j0] + h1 * su[33 + j0] + h2 * su[34 + j0] + h3 * su[35 + j0];
    float q2 = h0 * su[48 + j0] + h1 * su[49 + j0] + h2 * su[50 + j0] + h3 * su[51 + j0];

    // post-loop reconvergence point: full-warp xor reduce is safe here
    p1 += __shfl_xor_sync(FULL, p1, 1); p1 += __shfl_xor_sync(FULL, p1, 2);
    p2 += __shfl_xor_sync(FULL, p2, 1); p2 += __shfl_xor_sync(FULL, p2, 2);
    q1 += __shfl_xor_sync(FULL, q1, 1); q1 += __shfl_xor_sync(FULL, q1, 2);
    q2 += __shfl_xor_sync(FULL, q2, 1); q2 += __shfl_xor_sync(FULL, q2, 2);

    if (valid && c == 0) {
        g_p[n] = make_float2(p1, p2);
        g_q[n] = make_float2(q1, q2);
    }
}

// ---------------- K_gagg2: gather-aggregate p (MLP-4) + classifier scalars -
__global__ void k_gagg2() {
    int n = blockIdx.x * blockDim.x + threadIdx.x;
    if (n >= NN) return;
    int deg = g_degi[n];
    int end = g_row[n];
    int beg = end - deg;
    float ax = 0.f, ay = 0.f;
    int last = end - 1;
    for (int j = beg; j < end; j += 4) {
        int j1 = min(j + 1, last), j2 = min(j + 2, last), j3 = min(j + 3, last);
        int s0 = g_csr[j], s1 = g_csr[j1], s2 = g_csr[j2], s3 = g_csr[j3];
        float w1 = (j + 1 < end) ? 1.f : 0.f;
        float w2 = (j + 2 < end) ? 1.f : 0.f;
        float w3 = (j + 3 < end) ? 1.f : 0.f;
        float2 v0 = g_p[s0], v1 = g_p[s1], v2 = g_p[s2], v3 = g_p[s3];
        ax += v0.x + fmaf(w1, v1.x, fmaf(w2, v2.x, w3 * v3.x));
        ay += v0.y + fmaf(w1, v1.y, fmaf(w2, v2.y, w3 * v3.y));
    }
    float inv = g_inv[n];
    float2 q = g_q[n];
    g_s1[n] = ax * inv + q.x + g_u[64];
    g_s2[n] = ay * inv + q.y + g_u[65];
}

// ---------------- K_loss: logits + BCE, fused final reduce ------------------
__global__ void k_loss(const int* __restrict__ a1, const int* __restrict__ a2,
                       const int* __restrict__ labels, const float* __restrict__ bc,
                       float* __restrict__ out) {
    int tid = threadIdx.x;
    float acc = 0.f;
    float bias = bc[0];
    int i = blockIdx.x * 256 + tid;   // 64*256 == BB exactly
    {
        float l = g_s1[a1[i]] + g_s2[a2[i]] + bias;
        out[1 + i] = l;
        float y = (float)labels[i];
        acc += fmaxf(l, 0.f) - l * y + log1pf(expf(-fabsf(l)));
    }
    __shared__ float sred[256];
    __shared__ bool s_last;
    sred[tid] = acc;
    __syncthreads();
    for (int s = 128; s > 0; s >>= 1) {
        if (tid < s) sred[tid] += sred[tid + s];
        __syncthreads();
    }
    if (tid == 0) {
        g_partial[blockIdx.x] = sred[0];
        __threadfence();
        int v = atomicAdd(&g_done, 1);
        s_last = (v == 63);
    }
    __syncthreads();
    if (s_last) {
        float v = (tid < 64) ? g_partial[tid] : 0.f;
        sred[tid] = v;
        __syncthreads();
        for (int s = 32; s > 0; s >>= 1) {
            if (tid < s) sred[tid] += sred[tid + s];
            __syncthreads();
        }
        if (tid == 0) out[0] = sred[0] * (1.f / (float)BB);
    }
}

// ---------------- launch ----------------------------------------------------
extern "C" void kernel_launch(void* const* d_in, const int* in_sizes, int n_in,
                              void* d_out, int out_size) {
    const float* x    = (const float*)d_in[0];
    const float* w1l  = (const float*)d_in[1];
    const float* b1   = (const float*)d_in[2];
    const float* w1r  = (const float*)d_in[3];
    const float* w2l  = (const float*)d_in[4];
    const float* b2   = (const float*)d_in[5];
    const float* w2r  = (const float*)d_in[6];
    const float* wc   = (const float*)d_in[7];
    const float* bc   = (const float*)d_in[8];
    const int*   edge = (const int*)d_in[9];
    const int*   a1   = (const int*)d_in[10];
    const int*   a2   = (const int*)d_in[11];
    const int*   lab  = (const int*)d_in[12];
    float* out = (float*)d_out;

    const int* src = edge;
    const int* dst = edge + EE;

    k_init <<<99, 1024>>>(w2l, w2r, b2, wc);
    k_p1   <<<PROJ_A + DEG_BLOCKS, 256>>>(x, w1l, w1r, dst);
    k_scan <<<SCAN_BLOCKS, 1024>>>();
    k_p2   <<<FILL_BLOCKS + PROJ_B, 256>>>(x, w1l, w1r, src, dst);
    k_gagg1<<<(NN * 4 + 255) / 256, 256>>>(b1);
    k_gagg2<<<(NN + 255) / 256, 256>>>();
    k_loss <<<64, 256>>>(a1, a2, lab, bc, out);
}

// round 8
// speedup vs baseline: 1.5814x; 1.5814x over previous
#include <cuda_runtime.h>
#include <math.h>

#define NN 100000
#define DD 128
#define HH 16
#define EE 1600000
#define BB 16384
#define FULL 0xffffffffu

#define PROJ_BLOCKS ((NN + 127) / 128)      // 782
#define DEG_BLOCKS  ((EE / 4 + 255) / 256)  // 1563
#define SCAN_BLOCKS 98

typedef unsigned long long u64;

// ---------------- scratch (device globals) ---------------------------------
__device__ int    g_degi[NN];
__device__ int    g_incl[NN];
__device__ int    g_bsum[SCAN_BLOCKS];
__device__ int    g_boff[SCAN_BLOCKS];
__device__ int    g_row [NN];       // exclusive offsets; post-fill: end(n)
__device__ float  g_inv [NN];
__device__ int    g_csr [EE];
__device__ float  g_y1  [NN * HH];
__device__ float  g_z1  [NN * HH];
__device__ float2 g_p   [NN];
__device__ float2 g_q   [NN];
__device__ float  g_s1  [NN];
__device__ float  g_s2  [NN];
__device__ float  g_u   [66];
__device__ float  g_partial[64];
__device__ int    g_sdone;          // scanA completion counter
__device__ int    g_done;           // loss last-block counter

// f32x2 packed math (sm_100+)
#define PK(d, lo, hi)  asm("mov.b64 %0, {%1,%2};" : "=l"(d) : "f"(lo), "f"(hi))
#define UPK(lo, hi, s) asm("mov.b64 {%0,%1}, %2;" : "=f"(lo), "=f"(hi) : "l"(s))
#define FMA2(d, a, b)  asm("fma.rn.f32x2 %0, %1, %2, %0;" : "+l"(d) : "l"(a), "l"(b))

// ---------------- K_init: zero counters + prep collapsed weights -----------
__global__ void k_init(const float* __restrict__ w2l, const float* __restrict__ w2r,
                       const float* __restrict__ b2,  const float* __restrict__ wc) {
    if (blockIdx.x < 98) {
        int n = blockIdx.x * 1024 + threadIdx.x;
        if (n < NN) g_degi[n] = 0;
    } else {
        int t = threadIdx.x;
        if (t < 64) {
            int which = t >> 4, j = t & 15;
            const float* w = (which == 0 || which == 2) ? w2l : w2r;
            const float* c = (which < 2) ? wc : (wc + DD);
            float s = 0.f;
            for (int d = 0; d < DD; d++) s += w[j * DD + d] * c[d];
            g_u[which * 16 + j] = s;
        }
        if (t == 64) { float s = 0.f; for (int d = 0; d < DD; d++) s += b2[d] * wc[d];      g_u[64] = s; }
        if (t == 65) { float s = 0.f; for (int d = 0; d < DD; d++) s += b2[d] * wc[DD + d]; g_u[65] = s; }
        if (t == 66) g_sdone = 0;
        if (t == 67) g_done = 0;
    }
}

// ---------------- K_projdeg: proj GEMM blocks + degree-histogram blocks ----
__global__ void k_projdeg(const float* __restrict__ x,
                          const float* __restrict__ w1l,
                          const float* __restrict__ w1r,
                          const int*   __restrict__ dst) {
    __shared__ float sw[DD * 32];
    __shared__ float sxT[32 * 132];
    const int tid = threadIdx.x;

    if (blockIdx.x >= PROJ_BLOCKS) {
        int idx = (blockIdx.x - PROJ_BLOCKS) * 256 + tid;
        if (idx < EE / 4) {
            int4 d = reinterpret_cast<const int4*>(dst)[idx];
            atomicAdd(&g_degi[d.x], 1);
            atomicAdd(&g_degi[d.y], 1);
            atomicAdd(&g_degi[d.z], 1);
            atomicAdd(&g_degi[d.w], 1);
        }
        return;
    }

    for (int i = tid; i < DD * 32; i += 256) {
        int k = i >> 5, j = i & 31;
        sw[i] = (j < 16) ? w1l[k * HH + j] : w1r[k * HH + (j - 16)];
    }

    const int row0 = blockIdx.x * 128;
    const int rq = tid >> 3;
    const int g  = tid & 7;

    u64 accp[2][4];
#pragma unroll
    for (int i = 0; i < 2; i++)
#pragma unroll
        for (int j = 0; j < 4; j++) accp[i][j] = 0ull;

    const int rs = tid >> 3;
    const int q  = tid & 7;

    for (int kc = 0; kc < 4; kc++) {
        __syncthreads();
#pragma unroll
        for (int rr = rs; rr < 128; rr += 32) {
            int row = row0 + rr;
            float4 v = make_float4(0.f, 0.f, 0.f, 0.f);
            if (row < NN)
                v = reinterpret_cast<const float4*>(x + row * DD + kc * 32)[q];
            sxT[(q * 4 + 0) * 132 + rr] = v.x;
            sxT[(q * 4 + 1) * 132 + rr] = v.y;
            sxT[(q * 4 + 2) * 132 + rr] = v.z;
            sxT[(q * 4 + 3) * 132 + rr] = v.w;
        }
        __syncthreads();
#pragma unroll
        for (int kk = 0; kk < 32; kk++) {
            float4 xv = *reinterpret_cast<const float4*>(&sxT[kk * 132 + rq * 4]);
            float4 wv = *reinterpret_cast<const float4*>(&sw[(kc * 32 + kk) * 32 + g * 4]);
            u64 x01, x23, w0, w1, w2, w3;
            PK(x01, xv.x, xv.y);
            PK(x23, xv.z, xv.w);
            PK(w0, wv.x, wv.x);
            PK(w1, wv.y, wv.y);
            PK(w2, wv.z, wv.z);
            PK(w3, wv.w, wv.w);
            FMA2(accp[0][0], x01, w0); FMA2(accp[1][0], x23, w0);
            FMA2(accp[0][1], x01, w1); FMA2(accp[1][1], x23, w1);
            FMA2(accp[0][2], x01, w2); FMA2(accp[1][2], x23, w2);
            FMA2(accp[0][3], x01, w3); FMA2(accp[1][3], x23, w3);
        }
    }

    float acc[4][4];
#pragma unroll
    for (int j = 0; j < 4; j++) {
        UPK(acc[0][j], acc[1][j], accp[0][j]);
        UPK(acc[2][j], acc[3][j], accp[1][j]);
    }

#pragma unroll
    for (int i = 0; i < 4; i++) {
        int row = row0 + rq * 4 + i;
        if (row < NN) {
            float4 v = make_float4(acc[i][0], acc[i][1], acc[i][2], acc[i][3]);
            if (g < 4) reinterpret_cast<float4*>(g_y1 + row * HH)[g]     = v;
            else       reinterpret_cast<float4*>(g_z1 + row * HH)[g - 4] = v;
        }
    }
}

// ---------------- K_scanA: block scans + last block scans block totals -----
__global__ void k_scanA() {
    __shared__ int ws[32];
    __shared__ bool s_last;
    int tid = threadIdx.x, lane = tid & 31, w = tid >> 5;
    int n = blockIdx.x * 1024 + tid;
    int v = (n < NN) ? g_degi[n] : 0;
    int x = v;
#pragma unroll
    for (int o = 1; o < 32; o <<= 1) {
        int t = __shfl_up_sync(FULL, x, o);
        if (lane >= o) x += t;
    }
    if (lane == 31) ws[w] = x;
    __syncthreads();
    if (w == 0) {
        int b = ws[lane];
#pragma unroll
        for (int o = 1; o < 32; o <<= 1) {
            int t = __shfl_up_sync(FULL, b, o);
            if (lane >= o) b += t;
        }
        ws[lane] = b;
    }
    __syncthreads();
    int incl = x + (w > 0 ? ws[w - 1] : 0);
    if (n < NN) g_incl[n] = incl;
    if (tid == 1023) g_bsum[blockIdx.x] = incl;
    // last-arriving block scans the 98 block totals (fused scanB)
    if (tid == 0) {
        __threadfence();
        s_last = (atomicAdd(&g_sdone, 1) == SCAN_BLOCKS - 1);
    }
    __syncthreads();
    if (s_last && tid == 0) {
        int run = 0;
        for (int b = 0; b < SCAN_BLOCKS; b++) {
            g_boff[b] = run;
            run += g_bsum[b];
        }
    }
}

// ---------------- K_scanC: finalize row offsets + inv-deg ------------------
__global__ void k_scanC() {
    int n = blockIdx.x * blockDim.x + threadIdx.x;
    if (n >= NN) return;
    int d = g_degi[n];
    g_row[n] = g_incl[n] - d + g_boff[n >> 10];   // exclusive offset (cursor)
    g_inv[n] = 1.f / (float)max(d, 1);
}

// ---------------- K_fill: scatter edges into CSR (bumps g_row) -------------
__global__ void k_fill(const int* __restrict__ src, const int* __restrict__ dst) {
    int idx = blockIdx.x * blockDim.x + threadIdx.x;
    if (idx >= EE / 4) return;
    int4 s = reinterpret_cast<const int4*>(src)[idx];
    int4 d = reinterpret_cast<const int4*>(dst)[idx];
    int p0 = atomicAdd(&g_row[d.x], 1); g_csr[p0] = s.x;
    int p1 = atomicAdd(&g_row[d.y], 1); g_csr[p1] = s.y;
    int p2 = atomicAdd(&g_row[d.z], 1); g_csr[p2] = s.z;
    int p3 = atomicAdd(&g_row[d.w], 1); g_csr[p3] = s.w;
}

// ---------------- K_gagg1: quad-gather y1 + fused h + contraction ----------
// 4 threads per node; lane c handles components c*4..c*4+3. CSR indices
// loaded once per quad, broadcast with the QUAD mask (divergent loop!).
__global__ void k_gagg1(const float* __restrict__ b1) {
    __shared__ float su[64];
    __shared__ float sb[16];
    int tid = threadIdx.x;
    if (tid < 64) su[tid] = g_u[tid];
    if (tid < 16) sb[tid] = b1[tid];
    __syncthreads();

    int t = blockIdx.x * 256 + tid;
    int n = t >> 2, c = t & 3;
    bool valid = (n < NN);
    int ncl = valid ? n : (NN - 1);

    const unsigned qmask = 0xFu << (threadIdx.x & 28);

    int deg = g_degi[ncl];
    int end = g_row[ncl];                  // post-fill: end offset
    int beg = end - deg;
    float4 acc = make_float4(0.f, 0.f, 0.f, 0.f);
    int last = end - 1;
    for (int j = beg; j < end; j += 4) {
        int jj = min(j + c, last);
        int idx = g_csr[jj];
        int s0 = __shfl_sync(qmask, idx, 0, 4);
        int s1 = __shfl_sync(qmask, idx, 1, 4);
        int s2 = __shfl_sync(qmask, idx, 2, 4);
        int s3 = __shfl_sync(qmask, idx, 3, 4);
        float w1 = (j + 1 < end) ? 1.f : 0.f;
        float w2 = (j + 2 < end) ? 1.f : 0.f;
        float w3 = (j + 3 < end) ? 1.f : 0.f;
        float4 v0 = reinterpret_cast<const float4*>(g_y1 + (size_t)s0 * HH)[c];
        float4 v1 = reinterpret_cast<const float4*>(g_y1 + (size_t)s1 * HH)[c];
        float4 v2 = reinterpret_cast<const float4*>(g_y1 + (size_t)s2 * HH)[c];
        float4 v3 = reinterpret_cast<const float4*>(g_y1 + (size_t)s3 * HH)[c];
        acc.x += v0.x + fmaf(w1, v1.x, fmaf(w2, v2.x, w3 * v3.x));
        acc.y += v0.y + fmaf(w1, v1.y, fmaf(w2, v2.y, w3 * v3.y));
        acc.z += v0.z + fmaf(w1, v1.z, fmaf(w2, v2.z, w3 * v3.z));
        acc.w += v0.w + fmaf(w1, v1.w, fmaf(w2, v2.w, w3 * v3.w));
    }

    float inv = g_inv[ncl];
    float4 z = reinterpret_cast<const float4*>(g_z1 + (size_t)ncl * HH)[c];
    int j0 = c * 4;
    float h0 = fmaxf(acc.x * inv + sb[j0 + 0] + z.x, 0.f);
    float h1 = fmaxf(acc.y * inv + sb[j0 + 1] + z.y, 0.f);
    float h2 = fmaxf(acc.z * inv + sb[j0 + 2] + z.z, 0.f);
    float h3 = fmaxf(acc.w * inv + sb[j0 + 3] + z.w, 0.f);

    float p1 = h0 * su[j0]      + h1 * su[j0 + 1]  + h2 * su[j0 + 2]  + h3 * su[j0 + 3];
    float q1 = h0 * su[16 + j0] + h1 * su[17 + j0] + h2 * su[18 + j0] + h3 * su[19 + j0];
    float p2 = h0 * su[32 + j0] + h1 * su[33 + j0] + h2 * su[34 + j0] + h3 * su[35 + j0];
    float q2 = h0 * su[48 + j0] + h1 * su[49 + j0] + h2 * su[50 + j0] + h3 * su[51 + j0];

    // post-loop reconvergence: full-warp xor reduce is safe
    p1 += __shfl_xor_sync(FULL, p1, 1); p1 += __shfl_xor_sync(FULL, p1, 2);
    p2 += __shfl_xor_sync(FULL, p2, 1); p2 += __shfl_xor_sync(FULL, p2, 2);
    q1 += __shfl_xor_sync(FULL, q1, 1); q1 += __shfl_xor_sync(FULL, q1, 2);
    q2 += __shfl_xor_sync(FULL, q2, 1); q2 += __shfl_xor_sync(FULL, q2, 2);

    if (valid && c == 0) {
        g_p[n] = make_float2(p1, p2);
        g_q[n] = make_float2(q1, q2);
    }
}

// ---------------- K_gagg2: gather-aggregate p (MLP-4) + classifier scalars -
__global__ void k_gagg2() {
    int n = blockIdx.x * blockDim.x + threadIdx.x;
    if (n >= NN) return;
    int deg = g_degi[n];
    int end = g_row[n];
    int beg = end - deg;
    float ax = 0.f, ay = 0.f;
    int last = end - 1;
    for (int j = beg; j < end; j += 4) {
        int j1 = min(j + 1, last), j2 = min(j + 2, last), j3 = min(j + 3, last);
        int s0 = g_csr[j], s1 = g_csr[j1], s2 = g_csr[j2], s3 = g_csr[j3];
        float w1 = (j + 1 < end) ? 1.f : 0.f;
        float w2 = (j + 2 < end) ? 1.f : 0.f;
        float w3 = (j + 3 < end) ? 1.f : 0.f;
        float2 v0 = g_p[s0], v1 = g_p[s1], v2 = g_p[s2], v3 = g_p[s3];
        ax += v0.x + fmaf(w1, v1.x, fmaf(w2, v2.x, w3 * v3.x));
        ay += v0.y + fmaf(w1, v1.y, fmaf(w2, v2.y, w3 * v3.y));
    }
    float inv = g_inv[n];
    float2 q = g_q[n];
    g_s1[n] = ax * inv + q.x + g_u[64];
    g_s2[n] = ay * inv + q.y + g_u[65];
}

// ---------------- K_loss: logits + BCE, fused final reduce ------------------
__global__ void k_loss(const int* __restrict__ a1, const int* __restrict__ a2,
                       const int* __restrict__ labels, const float* __restrict__ bc,
                       float* __restrict__ out) {
    int tid = threadIdx.x;
    float bias = bc[0];
    int i = blockIdx.x * 256 + tid;   // 64*256 == BB exactly
    float l = g_s1[a1[i]] + g_s2[a2[i]] + bias;
    out[1 + i] = l;
    float y = (float)labels[i];
    float acc = fmaxf(l, 0.f) - l * y + log1pf(expf(-fabsf(l)));

    __shared__ float sred[256];
    __shared__ bool s_last;
    sred[tid] = acc;
    __syncthreads();
    for (int s = 128; s > 0; s >>= 1) {
        if (tid < s) sred[tid] += sred[tid + s];
        __syncthreads();
    }
    if (tid == 0) {
        g_partial[blockIdx.x] = sred[0];
        __threadfence();
        s_last = (atomicAdd(&g_done, 1) == 63);
    }
    __syncthreads();
    if (s_last) {
        float v = (tid < 64) ? g_partial[tid] : 0.f;
        sred[tid] = v;
        __syncthreads();
        for (int s = 32; s > 0; s >>= 1) {
            if (tid < s) sred[tid] += sred[tid + s];
            __syncthreads();
        }
        if (tid == 0) out[0] = sred[0] * (1.f / (float)BB);
    }
}

// ---------------- launch ----------------------------------------------------
extern "C" void kernel_launch(void* const* d_in, const int* in_sizes, int n_in,
                              void* d_out, int out_size) {
    const float* x    = (const float*)d_in[0];
    const float* w1l  = (const float*)d_in[1];
    const float* b1   = (const float*)d_in[2];
    const float* w1r  = (const float*)d_in[3];
    const float* w2l  = (const float*)d_in[4];
    const float* b2   = (const float*)d_in[5];
    const float* w2r  = (const float*)d_in[6];
    const float* wc   = (const float*)d_in[7];
    const float* bc   = (const float*)d_in[8];
    const int*   edge = (const int*)d_in[9];
    const int*   a1   = (const int*)d_in[10];
    const int*   a2   = (const int*)d_in[11];
    const int*   lab  = (const int*)d_in[12];
    float* out = (float*)d_out;

    const int* src = edge;
    const int* dst = edge + EE;

    k_init   <<<99, 1024>>>(w2l, w2r, b2, wc);
    k_projdeg<<<PROJ_BLOCKS + DEG_BLOCKS, 256>>>(x, w1l, w1r, dst);
    k_scanA  <<<SCAN_BLOCKS, 1024>>>();
    k_scanC  <<<(NN + 255) / 256, 256>>>();
    k_fill   <<<(EE / 4 + 255) / 256, 256>>>(src, dst);
    k_gagg1  <<<(NN * 4 + 255) / 256, 256>>>(b1);
    k_gagg2  <<<(NN + 255) / 256, 256>>>();
    k_loss   <<<64, 256>>>(a1, a2, lab, bc, out);
}